// round 1
// baseline (speedup 1.0000x reference)
#include <cuda_runtime.h>

// ShiftKernelMaker: input (128, 4096, 7, 7) fp32. For each of the 128*4096
// slices of 49 floats, output mask = (x == max(slice)) ? 1.0f : 0.0f.
// Pure streaming problem: 102.8 MB in + 102.8 MB out.
//
// Strategy: each 128-thread block stages 128 contiguous slices (6272 floats,
// 25088 bytes -> 16B aligned block base) into smem with coalesced float4
// loads, each thread reduces its own 49-float slice (stride 49 is odd ->
// bank-conflict-free), rewrites the mask in place, then streams back with
// coalesced float4 stores.

#define K_ELEMS 49
#define SLICES_PER_BLOCK 128
#define THREADS 128
#define FLOATS_PER_BLOCK (SLICES_PER_BLOCK * K_ELEMS)   // 6272
#define VEC4_PER_BLOCK (FLOATS_PER_BLOCK / 4)           // 1568

__global__ __launch_bounds__(THREADS) void shift_mask_kernel(
    const float* __restrict__ in, float* __restrict__ out)
{
    __shared__ float s[FLOATS_PER_BLOCK];

    const int t = threadIdx.x;
    const size_t base = (size_t)blockIdx.x * FLOATS_PER_BLOCK;

    // Coalesced float4 load: block base is 25088B-aligned (25088 % 16 == 0).
    const float4* __restrict__ gin = reinterpret_cast<const float4*>(in + base);
    float4* sv = reinterpret_cast<float4*>(s);

    #pragma unroll
    for (int i = t; i < VEC4_PER_BLOCK; i += THREADS) {
        sv[i] = gin[i];
    }
    __syncthreads();

    // Each thread owns one slice of 49 floats. smem index = t*49 + k:
    // stride 49 mod 32 hits all 32 banks (gcd(49,32)=1) -> conflict free.
    float* sp = s + t * K_ELEMS;

    float mx = sp[0];
    #pragma unroll
    for (int k = 1; k < K_ELEMS; k++) {
        mx = fmaxf(mx, sp[k]);
    }
    #pragma unroll
    for (int k = 0; k < K_ELEMS; k++) {
        sp[k] = (sp[k] == mx) ? 1.0f : 0.0f;
    }
    __syncthreads();

    // Coalesced float4 store.
    float4* __restrict__ gout = reinterpret_cast<float4*>(out + base);
    #pragma unroll
    for (int i = t; i < VEC4_PER_BLOCK; i += THREADS) {
        gout[i] = sv[i];
    }
}

extern "C" void kernel_launch(void* const* d_in, const int* in_sizes, int n_in,
                              void* d_out, int out_size)
{
    const float* in = (const float*)d_in[0];
    float* out = (float*)d_out;

    const int n = in_sizes[0];                 // 128*4096*49 = 25,690,112
    const int slices = n / K_ELEMS;            // 524,288
    const int blocks = slices / SLICES_PER_BLOCK;  // 4096 (exact)

    shift_mask_kernel<<<blocks, THREADS>>>(in, out);
}

// round 2
// speedup vs baseline: 1.1667x; 1.1667x over previous
#include <cuda_runtime.h>
#include <cstdint>

// ShiftKernelMaker: input (128, 4096, 7, 7) fp32. For each 49-float slice,
// output mask = (x == max(slice)). Pure streaming: 102.8 MB in + 102.8 MB out.
//
// R2 strategy: TMA (cp.async.bulk) for both directions. One elected thread
// per block issues a 25088B bulk G->S load against an mbarrier; 128 threads
// each reduce one 49-float slice out of smem (stride 49 -> conflict-free
// banks, gcd(49,32)=1), write the mask in place, then one bulk S->G store.
// No register staging, no per-thread LDG/STG -> issue pipe nearly idle,
// DRAM driven by the async proxy.

#define K_ELEMS 49
#define SLICES_PER_BLOCK 128
#define THREADS 128
#define TILE_FLOATS (SLICES_PER_BLOCK * K_ELEMS)   // 6272
#define TILE_BYTES (TILE_FLOATS * 4)               // 25088 (16B multiple)

__device__ __forceinline__ uint32_t smem_u32(const void* p) {
    uint32_t a;
    asm("{ .reg .u64 t; cvta.to.shared.u64 t, %1; cvt.u32.u64 %0, t; }"
        : "=r"(a) : "l"(p));
    return a;
}

__global__ __launch_bounds__(THREADS) void shift_mask_kernel(
    const float* __restrict__ in, float* __restrict__ out)
{
    __shared__ alignas(128) float s[TILE_FLOATS];
    __shared__ alignas(8) uint64_t mbar;

    const int t = threadIdx.x;
    const size_t base = (size_t)blockIdx.x * TILE_FLOATS;
    const uint32_t s_addr = smem_u32(s);
    const uint32_t mbar_addr = smem_u32(&mbar);

    if (t == 0) {
        asm volatile("mbarrier.init.shared.b64 [%0], 1;"
                     :: "r"(mbar_addr) : "memory");
    }
    __syncthreads();

    if (t == 0) {
        asm volatile("mbarrier.arrive.expect_tx.shared.b64 _, [%0], %1;"
                     :: "r"(mbar_addr), "r"((uint32_t)TILE_BYTES) : "memory");
        asm volatile(
            "cp.async.bulk.shared::cta.global.mbarrier::complete_tx::bytes "
            "[%0], [%1], %2, [%3];"
            :: "r"(s_addr), "l"(in + base), "r"((uint32_t)TILE_BYTES),
               "r"(mbar_addr) : "memory");
    }

    // All threads wait for the bulk load (phase parity 0, acquire).
    asm volatile(
        "{\n\t"
        ".reg .pred P;\n\t"
        "WL_%=:\n\t"
        "mbarrier.try_wait.parity.acquire.cta.shared::cta.b64 P, [%0], 0, 0x989680;\n\t"
        "@P bra WD_%=;\n\t"
        "bra WL_%=;\n\t"
        "WD_%=:\n\t"
        "}"
        :: "r"(mbar_addr) : "memory");

    // Each thread owns one 49-float slice; stride 49 is odd -> all 32 banks,
    // conflict-free scalar LDS/STS.
    float* sp = s + t * K_ELEMS;

    float mx = sp[0];
    #pragma unroll
    for (int k = 1; k < K_ELEMS; k++) {
        mx = fmaxf(mx, sp[k]);
    }
    #pragma unroll
    for (int k = 0; k < K_ELEMS; k++) {
        sp[k] = (sp[k] == mx) ? 1.0f : 0.0f;
    }
    __syncthreads();

    // Make generic-proxy STS visible to the async proxy, then bulk store.
    asm volatile("fence.proxy.async.shared::cta;" ::: "memory");
    if (t == 0) {
        asm volatile(
            "cp.async.bulk.global.shared::cta.bulk_group [%0], [%1], %2;"
            :: "l"(out + base), "r"(s_addr), "r"((uint32_t)TILE_BYTES)
            : "memory");
        asm volatile("cp.async.bulk.commit_group;" ::: "memory");
        // Must not let smem be reused by a successor block before the TMA
        // read of it completes.
        asm volatile("cp.async.bulk.wait_group.read 0;" ::: "memory");
    }
}

extern "C" void kernel_launch(void* const* d_in, const int* in_sizes, int n_in,
                              void* d_out, int out_size)
{
    const float* in = (const float*)d_in[0];
    float* out = (float*)d_out;

    const int n = in_sizes[0];                     // 25,690,112
    const int slices = n / K_ELEMS;                // 524,288
    const int blocks = slices / SLICES_PER_BLOCK;  // 4096 exact

    shift_mask_kernel<<<blocks, THREADS>>>(in, out);
}